// round 14
// baseline (speedup 1.0000x reference)
#include <cuda_runtime.h>
#include <cuda_bf16.h>
#include <math.h>
#include <stdint.h>

#define N_NODES 100000
#define N_EDGES 1600000
#define F_IN    256
#define HIDDEN  64
#define N_CLASS 2
#define N_BLKS  ((N_NODES + 255) / 256)     // 391 scan blocks

// ---------------- scratch (static __device__; 16B-aligned) ------------------
__device__ __align__(16) __nv_bfloat162 d_hbuf[N_NODES * 32];   // x@W1
__device__ __align__(16) __nv_bfloat162 d_hbuf2[N_NODES * 32];  // h1@W2
__device__ __align__(16) float d_h3[N_NODES * N_CLASS];         // h2@W3 (fp32)
__device__ float d_dinv[N_NODES];             // deg^{-1/2}
__device__ int   d_cnt[N_NODES];              // in-degree (no self loop)
__device__ int   d_scan[N_NODES];             // block-local inclusive scan
__device__ int   d_bsum[N_BLKS];              // per-block totals
__device__ int   d_boff[N_BLKS];              // exclusive block offsets
__device__ int   d_rowstart[N_NODES + 1];     // ORDERED exclusive prefix (CSR)
__device__ int   d_fillcur[N_NODES];          // fill cursors (copy of rowstart)
__device__ __align__(16) int2 d_csr[N_EDGES]; // (src, bitcast(dinv[src]))

// ---------------- CSR build: count -> exact prefix scan -> fill --------------
__global__ void k_count(const int4* __restrict__ dst4) {
    int t = blockIdx.x * blockDim.x + threadIdx.x;
    if (t < N_EDGES / 4) {
        int4 d = dst4[t];
        atomicAdd(&d_cnt[d.x], 1);
        atomicAdd(&d_cnt[d.y], 1);
        atomicAdd(&d_cnt[d.z], 1);
        atomicAdd(&d_cnt[d.w], 1);
    }
}

__global__ void k_scan_a() {          // block-local inclusive scan of cnt
    __shared__ int s[256];
    int b = blockIdx.x, t = threadIdx.x;
    int i = b * 256 + t;
    int v = (i < N_NODES) ? d_cnt[i] : 0;
    s[t] = v;
    __syncthreads();
    #pragma unroll
    for (int off = 1; off < 256; off <<= 1) {
        int x = (t >= off) ? s[t - off] : 0;
        __syncthreads();
        s[t] += x;
        __syncthreads();
    }
    if (i < N_NODES) d_scan[i] = s[t];
    if (t == 255) d_bsum[b] = s[255];
}

__global__ void k_scan_b() {          // single block: scan 391 block totals
    __shared__ int s[512];
    int t = threadIdx.x;
    int v = (t < N_BLKS) ? d_bsum[t] : 0;
    s[t] = v;
    __syncthreads();
    #pragma unroll
    for (int off = 1; off < 512; off <<= 1) {
        int x = (t >= off) ? s[t - off] : 0;
        __syncthreads();
        s[t] += x;
        __syncthreads();
    }
    if (t < N_BLKS) d_boff[t] = s[t] - v;   // exclusive
}

__global__ void k_scan_c() {          // rowstart (ordered!), dinv, fill cursors
    int i = blockIdx.x * blockDim.x + threadIdx.x;
    if (i < N_NODES) {
        int c  = d_cnt[i];
        int rs = d_boff[i >> 8] + d_scan[i] - c;   // exclusive prefix
        d_rowstart[i] = rs;
        d_fillcur[i]  = rs;
        d_dinv[i] = rsqrtf((float)(c + 1));        // +1 self loop
    }
    if (i == 0) d_rowstart[N_NODES] = N_EDGES;
}

__global__ void k_fill(const int4* __restrict__ src4, const int4* __restrict__ dst4) {
    int t = blockIdx.x * blockDim.x + threadIdx.x;
    if (t < N_EDGES / 4) {
        int4 s = src4[t];
        int4 d = dst4[t];
        int ss[4] = { s.x, s.y, s.z, s.w };
        int dd[4] = { d.x, d.y, d.z, d.w };
        float nsrc[4];
        #pragma unroll
        for (int c = 0; c < 4; c++) nsrc[c] = __ldg(&d_dinv[ss[c]]);
        #pragma unroll
        for (int c = 0; c < 4; c++) {
            int pos = atomicAdd(&d_fillcur[dd[c]], 1);
            d_csr[pos] = make_int2(ss[c], __float_as_int(nsrc[c]));
        }
    }
}

// ---------------- GEMM1 (tensor core, tf32): C[M,64] = A[M,256] @ W[256,64] --
__device__ __forceinline__ uint32_t smem_u32(const void* p) {
    return (uint32_t)__cvta_generic_to_shared(p);
}
__device__ __forceinline__ void cp_async16(uint32_t dst, const void* src) {
    asm volatile("cp.async.ca.shared.global [%0], [%1], 16;" :: "r"(dst), "l"(src));
}

__device__ __forceinline__ void mma_tf32(float c[4], uint32_t a0, uint32_t a1,
                                         uint32_t a2, uint32_t a3,
                                         uint32_t b0, uint32_t b1) {
    asm volatile(
        "mma.sync.aligned.m16n8k8.row.col.f32.tf32.tf32.f32 "
        "{%0,%1,%2,%3}, {%4,%5,%6,%7}, {%8,%9}, {%0,%1,%2,%3};"
        : "+f"(c[0]), "+f"(c[1]), "+f"(c[2]), "+f"(c[3])
        : "r"(a0), "r"(a1), "r"(a2), "r"(a3), "r"(b0), "r"(b1));
}

#define N_CHUNKS (F_IN / 32)
__global__ void k_gemm_tc(const float* __restrict__ A, const float* __restrict__ W,
                          __nv_bfloat162* __restrict__ C) {
    __shared__ uint32_t as[2][128][36];
    __shared__ uint32_t ws[2][32][72];
    const int tid  = threadIdx.x;
    const int wrp  = tid >> 5;
    const int lane = tid & 31;
    const int g    = lane >> 2;
    const int tg   = lane & 3;
    const int m0   = blockIdx.x * 128;

    const int ar = tid >> 3;
    const int ac = (tid & 7) * 4;
    const int wr = tid >> 4;
    const int wc = (tid & 15) * 4;

    int gr[4];
    #pragma unroll
    for (int i = 0; i < 4; i++) {
        int r = m0 + ar + 32 * i;
        gr[i] = (r < N_NODES) ? r : (N_NODES - 1);
    }

    auto stage = [&](int c, int buf) {
        const int k0 = c * 32;
        #pragma unroll
        for (int i = 0; i < 4; i++)
            cp_async16(smem_u32(&as[buf][ar + 32 * i][ac]),
                       &A[(size_t)gr[i] * F_IN + k0 + ac]);
        cp_async16(smem_u32(&ws[buf][wr][wc]),      &W[(size_t)(k0 + wr) * 64 + wc]);
        cp_async16(smem_u32(&ws[buf][wr + 16][wc]), &W[(size_t)(k0 + wr + 16) * 64 + wc]);
        asm volatile("cp.async.commit_group;");
    };

    float acc[8][4];
    #pragma unroll
    for (int j = 0; j < 8; j++)
        #pragma unroll
        for (int q = 0; q < 4; q++) acc[j][q] = 0.f;

    stage(0, 0);

    #pragma unroll
    for (int c = 0; c < N_CHUNKS; c++) {
        const int buf = c & 1;
        if (c + 1 < N_CHUNKS) {
            stage(c + 1, buf ^ 1);
            asm volatile("cp.async.wait_group 1;");
        } else {
            asm volatile("cp.async.wait_group 0;");
        }
        __syncthreads();

        #pragma unroll
        for (int kk = 0; kk < 32; kk += 8) {
            uint32_t a0 = as[buf][wrp * 16 + g][kk + tg];
            uint32_t a1 = as[buf][wrp * 16 + g + 8][kk + tg];
            uint32_t a2 = as[buf][wrp * 16 + g][kk + tg + 4];
            uint32_t a3 = as[buf][wrp * 16 + g + 8][kk + tg + 4];
            #pragma unroll
            for (int j = 0; j < 8; j++) {
                uint32_t b0 = ws[buf][kk + tg][8 * j + g];
                uint32_t b1 = ws[buf][kk + tg + 4][8 * j + g];
                mma_tf32(acc[j], a0, a1, a2, a3, b0, b1);
            }
        }
        __syncthreads();
    }

    const int row0 = m0 + wrp * 16 + g;
    #pragma unroll
    for (int j = 0; j < 8; j++) {
        int cp = 4 * j + tg;
        if (row0 < N_NODES)
            C[(size_t)row0 * 32 + cp] = __floats2bfloat162_rn(acc[j][0], acc[j][1]);
        if (row0 + 8 < N_NODES)
            C[(size_t)(row0 + 8) * 32 + cp] = __floats2bfloat162_rn(acc[j][2], acc[j][3]);
    }
}

// ---------------- staged warp aggregation core (bf16 features) ---------------
// CSR rows are node-contiguous (ordered rowstart); block pre-stages its CSR
// range in smem. Edge chain: LDS(csr) -> LDG(feature) instead of LDG -> LDG.
__device__ __forceinline__ float4 agg_node_staged(
    const __nv_bfloat162* __restrict__ h, int i, int h5, int l16,
    const int2* __restrict__ cs, int staged, int estart) {
    const float di = d_dinv[i];
    const int b = d_rowstart[i];
    const int n = d_rowstart[i + 1] - b;
    const int lb = b - estart;

    float4 acc = make_float4(0.f, 0.f, 0.f, 0.f);
    if (h5 == 0) {                         // self loop (weight di, ×di later)
        uint2 raw = *(const uint2*)&h[(size_t)i * 32 + l16 * 2];
        float2 u0 = __bfloat1622float2(*(__nv_bfloat162*)&raw.x);
        float2 u1 = __bfloat1622float2(*(__nv_bfloat162*)&raw.y);
        acc.x = u0.x * di; acc.y = u0.y * di; acc.z = u1.x * di; acc.w = u1.y * di;
    }
    #pragma unroll 4
    for (int e = h5; e < n; e += 2) {
        int idx = lb + e;
        int2 sn;
        if (idx < staged) sn = cs[idx];
        else              sn = d_csr[estart + idx];
        float ds = __int_as_float(sn.y);
        uint2 raw = *(const uint2*)&h[(size_t)sn.x * 32 + l16 * 2];
        float2 u0 = __bfloat1622float2(*(__nv_bfloat162*)&raw.x);
        float2 u1 = __bfloat1622float2(*(__nv_bfloat162*)&raw.y);
        acc.x = fmaf(u0.x, ds, acc.x);
        acc.y = fmaf(u0.y, ds, acc.y);
        acc.z = fmaf(u1.x, ds, acc.z);
        acc.w = fmaf(u1.y, ds, acc.w);
    }
    acc.x += __shfl_xor_sync(0xFFFFFFFFu, acc.x, 16);
    acc.y += __shfl_xor_sync(0xFFFFFFFFu, acc.y, 16);
    acc.z += __shfl_xor_sync(0xFFFFFFFFu, acc.z, 16);
    acc.w += __shfl_xor_sync(0xFFFFFFFFu, acc.w, 16);
    acc.x *= di; acc.y *= di; acc.z *= di; acc.w *= di;
    return acc;
}

// ---------------- fused: agg(hbuf)+b1+relu -> @W2 -> hbuf2 (bf16) ------------
#define CS_CAP 1536   // 64 nodes: mean 1024, sigma 32; +16σ cap, global fallback
__global__ void k_agg_gemm(const __nv_bfloat162* __restrict__ hin,
                           const float* __restrict__ bias,
                           const float* __restrict__ W2,
                           __nv_bfloat162* __restrict__ hout) {
    __shared__ float as[64][65];
    __shared__ float ws[64][64];
    __shared__ int2  cs[CS_CAP];
    const int tid  = threadIdx.x;
    const int wid  = tid >> 5;
    const int lane = tid & 31;
    const int h5   = lane >> 4;
    const int l16  = lane & 15;
    const int m0   = blockIdx.x * 64;
    const int mend = min(m0 + 64, N_NODES);

    const int estart = d_rowstart[m0];
    const int staged = min(d_rowstart[mend] - estart, CS_CAP);
    for (int t = tid; t < staged; t += 256)
        cs[t] = d_csr[estart + t];

    #pragma unroll
    for (int t = tid; t < 1024; t += 256) {
        int r  = t >> 4;
        int cc = (t & 15) * 4;
        *(float4*)&ws[r][cc] = *(const float4*)&W2[(size_t)r * 64 + cc];
    }
    __syncthreads();                      // cs ready before phase 1

    float4 b4 = *(const float4*)&bias[l16 * 4];

    #pragma unroll
    for (int q = 0; q < 8; q++) {
        int local = wid * 8 + q;
        int i = m0 + local;
        float4 v = make_float4(0.f, 0.f, 0.f, 0.f);
        if (i < N_NODES) {
            float4 acc = agg_node_staged(hin, i, h5, l16, cs, staged, estart);
            v.x = fmaxf(acc.x + b4.x, 0.f);
            v.y = fmaxf(acc.y + b4.y, 0.f);
            v.z = fmaxf(acc.z + b4.z, 0.f);
            v.w = fmaxf(acc.w + b4.w, 0.f);
        }
        if (h5 == 0) {
            as[local][l16 * 4 + 0] = v.x;
            as[local][l16 * 4 + 1] = v.y;
            as[local][l16 * 4 + 2] = v.z;
            as[local][l16 * 4 + 3] = v.w;
        }
    }
    __syncthreads();

    const int tx = tid & 15;
    const int ty = tid >> 4;
    float acc[4][4] = {};
    #pragma unroll
    for (int kk = 0; kk < 64; kk++) {
        float a[4];
        #pragma unroll
        for (int i = 0; i < 4; i++) a[i] = as[ty + 16 * i][kk];
        float b0 = ws[kk][2 * tx];
        float b1 = ws[kk][2 * tx + 1];
        float b2 = ws[kk][2 * tx + 32];
        float b3 = ws[kk][2 * tx + 33];
        #pragma unroll
        for (int i = 0; i < 4; i++) {
            acc[i][0] = fmaf(a[i], b0, acc[i][0]);
            acc[i][1] = fmaf(a[i], b1, acc[i][1]);
            acc[i][2] = fmaf(a[i], b2, acc[i][2]);
            acc[i][3] = fmaf(a[i], b3, acc[i][3]);
        }
    }
    #pragma unroll
    for (int i = 0; i < 4; i++) {
        int gr = m0 + ty + 16 * i;
        if (gr < N_NODES) {
            hout[(size_t)gr * 32 + tx]      = __floats2bfloat162_rn(acc[i][0], acc[i][1]);
            hout[(size_t)gr * 32 + 16 + tx] = __floats2bfloat162_rn(acc[i][2], acc[i][3]);
        }
    }
}

// ---------------- fused: agg(hbuf2)+b2+relu -> @W3 -> h3 ---------------------
#define CS3_CAP 512    // 8 nodes: mean 128, sigma 11; huge margin
__global__ void k_agg_gemm3(const __nv_bfloat162* __restrict__ hin,
                            const float* __restrict__ bias,
                            const float* __restrict__ W3,
                            float* __restrict__ h3) {
    __shared__ int2 cs[CS3_CAP];
    const int i0 = blockIdx.x * 8;
    const int iend = min(i0 + 8, N_NODES);
    const int estart = d_rowstart[min(i0, N_NODES)];
    const int staged = min(d_rowstart[iend] - estart, CS3_CAP);
    for (int t = threadIdx.x; t < staged; t += 256)
        cs[t] = d_csr[estart + t];
    __syncthreads();

    const int lane = threadIdx.x & 31;
    const int i = i0 + (threadIdx.x >> 5);
    if (i >= N_NODES) return;
    const int h5  = lane >> 4;
    const int l16 = lane & 15;

    float w3v[4];
    #pragma unroll
    for (int j = 0; j < 4; j++)
        w3v[j] = __ldg(&W3[(l16 * 4 + j) * 2 + h5]);
    float4 b4 = *(const float4*)&bias[l16 * 4];

    float4 acc = agg_node_staged(hin, i, h5, l16, cs, staged, estart);
    float4 v;
    v.x = fmaxf(acc.x + b4.x, 0.f);
    v.y = fmaxf(acc.y + b4.y, 0.f);
    v.z = fmaxf(acc.z + b4.z, 0.f);
    v.w = fmaxf(acc.w + b4.w, 0.f);

    float p = v.x * w3v[0] + v.y * w3v[1] + v.z * w3v[2] + v.w * w3v[3];
    #pragma unroll
    for (int off = 8; off > 0; off >>= 1)
        p += __shfl_xor_sync(0xFFFFFFFFu, p, off);
    if (l16 == 0)
        h3[(size_t)i * 2 + h5] = p;
}

// ---------------- layer-3 aggregation + bias + log_softmax ------------------
__global__ void k_agg3(const float* __restrict__ h3, const float* __restrict__ b3,
                       float* __restrict__ out) {
    __shared__ int2 cs[CS3_CAP];
    const int i0 = blockIdx.x * 8;
    const int iend = min(i0 + 8, N_NODES);
    const int estart = d_rowstart[min(i0, N_NODES)];
    const int staged = min(d_rowstart[iend] - estart, CS3_CAP);
    for (int t = threadIdx.x; t < staged; t += 256)
        cs[t] = d_csr[estart + t];
    __syncthreads();

    const int lane = threadIdx.x & 31;
    const int i = i0 + (threadIdx.x >> 5);
    if (i >= N_NODES) return;

    const float di = d_dinv[i];
    const int b = d_rowstart[i];
    const int n = d_rowstart[i + 1] - b;
    const int lb = b - estart;

    float a0 = 0.f, a1 = 0.f;
    for (int e = lane; e < n; e += 32) {
        int idx = lb + e;
        int2 sn;
        if (idx < staged) sn = cs[idx];
        else              sn = d_csr[estart + idx];
        float ds = __int_as_float(sn.y);
        float2 hh = *(const float2*)&h3[(size_t)sn.x * 2];
        a0 = fmaf(hh.x, ds, a0);
        a1 = fmaf(hh.y, ds, a1);
    }
    #pragma unroll
    for (int off = 16; off > 0; off >>= 1) {
        a0 += __shfl_down_sync(0xFFFFFFFFu, a0, off);
        a1 += __shfl_down_sync(0xFFFFFFFFu, a1, off);
    }
    if (lane == 0) {
        a0 = a0 * di + h3[(size_t)i * 2 + 0] * (di * di) + b3[0];
        a1 = a1 * di + h3[(size_t)i * 2 + 1] * (di * di) + b3[1];
        float m = fmaxf(a0, a1);
        float lse = m + logf(expf(a0 - m) + expf(a1 - m));
        out[(size_t)i * 2 + 0] = a0 - lse;
        out[(size_t)i * 2 + 1] = a1 - lse;
    }
}

// ---------------- launch -----------------------------------------------------
extern "C" void kernel_launch(void* const* d_in, const int* in_sizes, int n_in,
                              void* d_out, int out_size) {
    const float* x  = (const float*)d_in[0];
    const int*   ei = (const int*)d_in[1];
    const float* W1 = (const float*)d_in[2];
    const float* b1 = (const float*)d_in[3];
    const float* W2 = (const float*)d_in[4];
    const float* b2 = (const float*)d_in[5];
    const float* W3 = (const float*)d_in[6];
    const float* b3 = (const float*)d_in[7];
    float* out = (float*)d_out;

    const int4* src4 = (const int4*)ei;
    const int4* dst4 = (const int4*)(ei + N_EDGES);

    void *p_cnt, *p_hbuf, *p_hbuf2, *p_h3;
    cudaGetSymbolAddress(&p_cnt, d_cnt);
    cudaGetSymbolAddress(&p_hbuf, d_hbuf);
    cudaGetSymbolAddress(&p_hbuf2, d_hbuf2);
    cudaGetSymbolAddress(&p_h3, d_h3);

    const int NB_E4 = (N_EDGES / 4 + 255) / 256;
    const int NB_N  = (N_NODES + 255) / 256;
    const int NB_T  = (N_NODES + 127) / 128;
    const int NB_M  = (N_NODES + 63) / 64;
    const int NB_8  = (N_NODES + 7) / 8;     // 8 nodes per 256-thread block

    // fork: gemm_tc (x,W1 only) runs concurrently with the CSR build
    cudaStream_t s2;
    cudaStreamCreateWithFlags(&s2, cudaStreamNonBlocking);
    cudaEvent_t evFork, evJoin;
    cudaEventCreateWithFlags(&evFork, cudaEventDisableTiming);
    cudaEventCreateWithFlags(&evJoin, cudaEventDisableTiming);

    cudaEventRecord(evFork, 0);
    cudaStreamWaitEvent(s2, evFork, 0);
    k_gemm_tc<<<NB_T, 256, 0, s2>>>(x, W1, (__nv_bfloat162*)p_hbuf);
    cudaEventRecord(evJoin, s2);

    // CSR build on the main (capture) stream: count -> exact scan -> fill
    cudaMemsetAsync(p_cnt, 0, N_NODES * sizeof(int));
    k_count<<<NB_E4, 256>>>(dst4);
    k_scan_a<<<N_BLKS, 256>>>();
    k_scan_b<<<1, 512>>>();
    k_scan_c<<<NB_N, 256>>>();
    k_fill<<<NB_E4, 256>>>(src4, dst4);

    // join: aggregation needs both CSR and hbuf
    cudaStreamWaitEvent(0, evJoin, 0);

    k_agg_gemm<<<NB_M, 256>>>((const __nv_bfloat162*)p_hbuf, b1, W2,
                              (__nv_bfloat162*)p_hbuf2);
    k_agg_gemm3<<<NB_8, 256>>>((const __nv_bfloat162*)p_hbuf2, b2, W3, (float*)p_h3);
    k_agg3<<<NB_8, 256>>>((const float*)p_h3, b3, out);

    cudaEventDestroy(evFork);
    cudaEventDestroy(evJoin);
    cudaStreamDestroy(s2);
}

// round 15
// speedup vs baseline: 1.1269x; 1.1269x over previous
#include <cuda_runtime.h>
#include <cuda_bf16.h>
#include <math.h>
#include <stdint.h>

#define N_NODES 100000
#define N_EDGES 1600000
#define F_IN    256
#define HIDDEN  64
#define N_CLASS 2

// ---------------- scratch (static __device__; 16B-aligned) ------------------
__device__ __align__(16) __nv_bfloat162 d_hbuf[N_NODES * 32];   // x@W1
__device__ __align__(16) __nv_bfloat162 d_hbuf2[N_NODES * 32];  // h1@W2
__device__ __align__(16) float d_h3[N_NODES * N_CLASS];         // h2@W3 (fp32)
__device__ float d_dinv[N_NODES];             // deg^{-1/2}
// d_cnt is zero at module load; every call re-zeroes it in k_agg3 (last reader)
// so no memset is needed on the critical path.
__device__ int   d_cnt[N_NODES];              // in-degree (no self loop)
__device__ int   d_rowstart[N_NODES];         // CSR cursor: start, then end after fill
__device__ __align__(16) int2 d_csr[N_EDGES]; // (src, bitcast(dinv[src])) per edge
__device__ int   d_cursor;

// ---------------- CSR build -------------------------------------------------
__global__ void k_count(const int4* __restrict__ dst4) {
    int t = blockIdx.x * blockDim.x + threadIdx.x;
    if (t == 0) d_cursor = 0;
    if (t < N_EDGES / 4) {
        int4 d = dst4[t];
        atomicAdd(&d_cnt[d.x], 1);
        atomicAdd(&d_cnt[d.y], 1);
        atomicAdd(&d_cnt[d.z], 1);
        atomicAdd(&d_cnt[d.w], 1);
    }
}

__global__ void k_node() {
    int i = blockIdx.x * blockDim.x + threadIdx.x;
    if (i < N_NODES) {
        int c = d_cnt[i];
        d_dinv[i] = rsqrtf((float)(c + 1));          // +1 self loop
        d_rowstart[i] = atomicAdd(&d_cursor, c);
    }
}

// fill bumps d_rowstart in place; afterwards rowstart[i] = row END.
__global__ void k_fill(const int4* __restrict__ src4, const int4* __restrict__ dst4) {
    int t = blockIdx.x * blockDim.x + threadIdx.x;
    if (t < N_EDGES / 4) {
        int4 s = src4[t];
        int4 d = dst4[t];
        int ss[4] = { s.x, s.y, s.z, s.w };
        int dd[4] = { d.x, d.y, d.z, d.w };
        float nsrc[4];
        #pragma unroll
        for (int c = 0; c < 4; c++) nsrc[c] = __ldg(&d_dinv[ss[c]]);
        #pragma unroll
        for (int c = 0; c < 4; c++) {
            int pos = atomicAdd(&d_rowstart[dd[c]], 1);
            d_csr[pos] = make_int2(ss[c], __float_as_int(nsrc[c]));
        }
    }
}

// ---------------- GEMM1 (tensor core, tf32): C[M,64] = A[M,256] @ W[256,64] --
__device__ __forceinline__ uint32_t smem_u32(const void* p) {
    return (uint32_t)__cvta_generic_to_shared(p);
}
__device__ __forceinline__ void cp_async16(uint32_t dst, const void* src) {
    asm volatile("cp.async.ca.shared.global [%0], [%1], 16;" :: "r"(dst), "l"(src));
}

__device__ __forceinline__ void mma_tf32(float c[4], uint32_t a0, uint32_t a1,
                                         uint32_t a2, uint32_t a3,
                                         uint32_t b0, uint32_t b1) {
    asm volatile(
        "mma.sync.aligned.m16n8k8.row.col.f32.tf32.tf32.f32 "
        "{%0,%1,%2,%3}, {%4,%5,%6,%7}, {%8,%9}, {%0,%1,%2,%3};"
        : "+f"(c[0]), "+f"(c[1]), "+f"(c[2]), "+f"(c[3])
        : "r"(a0), "r"(a1), "r"(a2), "r"(a3), "r"(b0), "r"(b1));
}

#define N_CHUNKS (F_IN / 32)
__global__ void k_gemm_tc(const float* __restrict__ A, const float* __restrict__ W,
                          __nv_bfloat162* __restrict__ C) {
    __shared__ uint32_t as[2][128][36];
    __shared__ uint32_t ws[2][32][72];
    const int tid  = threadIdx.x;
    const int wrp  = tid >> 5;
    const int lane = tid & 31;
    const int g    = lane >> 2;
    const int tg   = lane & 3;
    const int m0   = blockIdx.x * 128;

    const int ar = tid >> 3;
    const int ac = (tid & 7) * 4;
    const int wr = tid >> 4;
    const int wc = (tid & 15) * 4;

    int gr[4];
    #pragma unroll
    for (int i = 0; i < 4; i++) {
        int r = m0 + ar + 32 * i;
        gr[i] = (r < N_NODES) ? r : (N_NODES - 1);
    }

    auto stage = [&](int c, int buf) {
        const int k0 = c * 32;
        #pragma unroll
        for (int i = 0; i < 4; i++)
            cp_async16(smem_u32(&as[buf][ar + 32 * i][ac]),
                       &A[(size_t)gr[i] * F_IN + k0 + ac]);
        cp_async16(smem_u32(&ws[buf][wr][wc]),      &W[(size_t)(k0 + wr) * 64 + wc]);
        cp_async16(smem_u32(&ws[buf][wr + 16][wc]), &W[(size_t)(k0 + wr + 16) * 64 + wc]);
        asm volatile("cp.async.commit_group;");
    };

    float acc[8][4];
    #pragma unroll
    for (int j = 0; j < 8; j++)
        #pragma unroll
        for (int q = 0; q < 4; q++) acc[j][q] = 0.f;

    stage(0, 0);

    #pragma unroll
    for (int c = 0; c < N_CHUNKS; c++) {
        const int buf = c & 1;
        if (c + 1 < N_CHUNKS) {
            stage(c + 1, buf ^ 1);
            asm volatile("cp.async.wait_group 1;");
        } else {
            asm volatile("cp.async.wait_group 0;");
        }
        __syncthreads();

        #pragma unroll
        for (int kk = 0; kk < 32; kk += 8) {
            uint32_t a0 = as[buf][wrp * 16 + g][kk + tg];
            uint32_t a1 = as[buf][wrp * 16 + g + 8][kk + tg];
            uint32_t a2 = as[buf][wrp * 16 + g][kk + tg + 4];
            uint32_t a3 = as[buf][wrp * 16 + g + 8][kk + tg + 4];
            #pragma unroll
            for (int j = 0; j < 8; j++) {
                uint32_t b0 = ws[buf][kk + tg][8 * j + g];
                uint32_t b1 = ws[buf][kk + tg + 4][8 * j + g];
                mma_tf32(acc[j], a0, a1, a2, a3, b0, b1);
            }
        }
        __syncthreads();
    }

    const int row0 = m0 + wrp * 16 + g;
    #pragma unroll
    for (int j = 0; j < 8; j++) {
        int cp = 4 * j + tg;
        if (row0 < N_NODES)
            C[(size_t)row0 * 32 + cp] = __floats2bfloat162_rn(acc[j][0], acc[j][1]);
        if (row0 + 8 < N_NODES)
            C[(size_t)(row0 + 8) * 32 + cp] = __floats2bfloat162_rn(acc[j][2], acc[j][3]);
    }
}

// ---------------- warp aggregation core (single node; bf16 features) ---------
__device__ __forceinline__ float4 agg_node(const __nv_bfloat162* __restrict__ h,
                                           int i, int h5, int l16) {
    const float di = d_dinv[i];
    const int n    = d_cnt[i];
    const int base = d_rowstart[i] - n;

    float4 acc = make_float4(0.f, 0.f, 0.f, 0.f);
    if (h5 == 0) {
        uint2 raw = *(const uint2*)&h[(size_t)i * 32 + l16 * 2];
        float2 u0 = __bfloat1622float2(*(__nv_bfloat162*)&raw.x);
        float2 u1 = __bfloat1622float2(*(__nv_bfloat162*)&raw.y);
        acc.x = u0.x * di; acc.y = u0.y * di; acc.z = u1.x * di; acc.w = u1.y * di;
    }
    #pragma unroll 4
    for (int e = h5; e < n; e += 2) {
        int2 sn = d_csr[base + e];
        float ds = __int_as_float(sn.y);
        uint2 raw = *(const uint2*)&h[(size_t)sn.x * 32 + l16 * 2];
        float2 u0 = __bfloat1622float2(*(__nv_bfloat162*)&raw.x);
        float2 u1 = __bfloat1622float2(*(__nv_bfloat162*)&raw.y);
        acc.x = fmaf(u0.x, ds, acc.x);
        acc.y = fmaf(u0.y, ds, acc.y);
        acc.z = fmaf(u1.x, ds, acc.z);
        acc.w = fmaf(u1.y, ds, acc.w);
    }
    acc.x += __shfl_xor_sync(0xFFFFFFFFu, acc.x, 16);
    acc.y += __shfl_xor_sync(0xFFFFFFFFu, acc.y, 16);
    acc.z += __shfl_xor_sync(0xFFFFFFFFu, acc.z, 16);
    acc.w += __shfl_xor_sync(0xFFFFFFFFu, acc.w, 16);
    acc.x *= di; acc.y *= di; acc.z *= di; acc.w *= di;
    return acc;
}

// ---------------- fused: agg(hbuf)+b1+relu -> @W2 -> hbuf2 (bf16) ------------
__global__ void k_agg_gemm(const __nv_bfloat162* __restrict__ hin,
                           const float* __restrict__ bias,
                           const float* __restrict__ W2,
                           __nv_bfloat162* __restrict__ hout) {
    __shared__ float as[64][65];
    __shared__ float ws[64][64];
    const int tid  = threadIdx.x;
    const int wid  = tid >> 5;
    const int lane = tid & 31;
    const int h5   = lane >> 4;
    const int l16  = lane & 15;
    const int m0   = blockIdx.x * 64;

    #pragma unroll
    for (int t = tid; t < 1024; t += 256) {
        int r  = t >> 4;
        int cc = (t & 15) * 4;
        *(float4*)&ws[r][cc] = *(const float4*)&W2[(size_t)r * 64 + cc];
    }

    float4 b4 = *(const float4*)&bias[l16 * 4];

    #pragma unroll
    for (int q = 0; q < 8; q++) {
        int local = wid * 8 + q;
        int i = m0 + local;
        float4 v = make_float4(0.f, 0.f, 0.f, 0.f);
        if (i < N_NODES) {
            float4 acc = agg_node(hin, i, h5, l16);
            v.x = fmaxf(acc.x + b4.x, 0.f);
            v.y = fmaxf(acc.y + b4.y, 0.f);
            v.z = fmaxf(acc.z + b4.z, 0.f);
            v.w = fmaxf(acc.w + b4.w, 0.f);
        }
        if (h5 == 0) {
            as[local][l16 * 4 + 0] = v.x;
            as[local][l16 * 4 + 1] = v.y;
            as[local][l16 * 4 + 2] = v.z;
            as[local][l16 * 4 + 3] = v.w;
        }
    }
    __syncthreads();

    const int tx = tid & 15;
    const int ty = tid >> 4;
    float acc[4][4] = {};
    #pragma unroll
    for (int kk = 0; kk < 64; kk++) {
        float a[4];
        #pragma unroll
        for (int i = 0; i < 4; i++) a[i] = as[ty + 16 * i][kk];
        float b0 = ws[kk][2 * tx];
        float b1 = ws[kk][2 * tx + 1];
        float b2 = ws[kk][2 * tx + 32];
        float b3 = ws[kk][2 * tx + 33];
        #pragma unroll
        for (int i = 0; i < 4; i++) {
            acc[i][0] = fmaf(a[i], b0, acc[i][0]);
            acc[i][1] = fmaf(a[i], b1, acc[i][1]);
            acc[i][2] = fmaf(a[i], b2, acc[i][2]);
            acc[i][3] = fmaf(a[i], b3, acc[i][3]);
        }
    }
    #pragma unroll
    for (int i = 0; i < 4; i++) {
        int gr = m0 + ty + 16 * i;
        if (gr < N_NODES) {
            hout[(size_t)gr * 32 + tx]      = __floats2bfloat162_rn(acc[i][0], acc[i][1]);
            hout[(size_t)gr * 32 + 16 + tx] = __floats2bfloat162_rn(acc[i][2], acc[i][3]);
        }
    }
}

// ---------------- fused: agg(hbuf2)+b2+relu -> @W3 -> h3 ---------------------
__global__ void k_agg_gemm3(const __nv_bfloat162* __restrict__ hin,
                            const float* __restrict__ bias,
                            const float* __restrict__ W3,
                            float* __restrict__ h3) {
    const int gwarp = (blockIdx.x * blockDim.x + threadIdx.x) >> 5;
    const int lane  = threadIdx.x & 31;
    if (gwarp >= N_NODES) return;
    const int i   = gwarp;
    const int h5  = lane >> 4;
    const int l16 = lane & 15;

    float w3v[4];
    #pragma unroll
    for (int j = 0; j < 4; j++)
        w3v[j] = __ldg(&W3[(l16 * 4 + j) * 2 + h5]);
    float4 b4 = *(const float4*)&bias[l16 * 4];

    float4 acc = agg_node(hin, i, h5, l16);
    float4 v;
    v.x = fmaxf(acc.x + b4.x, 0.f);
    v.y = fmaxf(acc.y + b4.y, 0.f);
    v.z = fmaxf(acc.z + b4.z, 0.f);
    v.w = fmaxf(acc.w + b4.w, 0.f);

    float p = v.x * w3v[0] + v.y * w3v[1] + v.z * w3v[2] + v.w * w3v[3];
    #pragma unroll
    for (int off = 8; off > 0; off >>= 1)
        p += __shfl_xor_sync(0xFFFFFFFFu, p, off);
    if (l16 == 0)
        h3[(size_t)i * 2 + h5] = p;
}

// ---------------- layer-3 aggregation + bias + log_softmax ------------------
// Also re-zeroes d_cnt (last reader) so the next call needs no memset.
__global__ void k_agg3(const float* __restrict__ h3, const float* __restrict__ b3,
                       float* __restrict__ out) {
    const int gwarp = (blockIdx.x * blockDim.x + threadIdx.x) >> 5;
    const int lane  = threadIdx.x & 31;
    if (gwarp >= N_NODES) return;
    const int i = gwarp;

    const float di = d_dinv[i];
    const int n    = d_cnt[i];
    const int base = d_rowstart[i] - n;

    float a0 = 0.f, a1 = 0.f;
    for (int e = lane; e < n; e += 32) {
        int2 sn = d_csr[base + e];
        float ds = __int_as_float(sn.y);
        float2 hh = *(const float2*)&h3[(size_t)sn.x * 2];
        a0 = fmaf(hh.x, ds, a0);
        a1 = fmaf(hh.y, ds, a1);
    }
    #pragma unroll
    for (int off = 16; off > 0; off >>= 1) {
        a0 += __shfl_down_sync(0xFFFFFFFFu, a0, off);
        a1 += __shfl_down_sync(0xFFFFFFFFu, a1, off);
    }
    if (lane == 0) {
        d_cnt[i] = 0;                     // reset for the next call (no memset)
        a0 = a0 * di + h3[(size_t)i * 2 + 0] * (di * di) + b3[0];
        a1 = a1 * di + h3[(size_t)i * 2 + 1] * (di * di) + b3[1];
        float m = fmaxf(a0, a1);
        float lse = m + logf(expf(a0 - m) + expf(a1 - m));
        out[(size_t)i * 2 + 0] = a0 - lse;
        out[(size_t)i * 2 + 1] = a1 - lse;
    }
}

// ---------------- launch -----------------------------------------------------
extern "C" void kernel_launch(void* const* d_in, const int* in_sizes, int n_in,
                              void* d_out, int out_size) {
    const float* x  = (const float*)d_in[0];
    const int*   ei = (const int*)d_in[1];
    const float* W1 = (const float*)d_in[2];
    const float* b1 = (const float*)d_in[3];
    const float* W2 = (const float*)d_in[4];
    const float* b2 = (const float*)d_in[5];
    const float* W3 = (const float*)d_in[6];
    const float* b3 = (const float*)d_in[7];
    float* out = (float*)d_out;

    const int4* src4 = (const int4*)ei;
    const int4* dst4 = (const int4*)(ei + N_EDGES);

    void *p_hbuf, *p_hbuf2, *p_h3;
    cudaGetSymbolAddress(&p_hbuf, d_hbuf);
    cudaGetSymbolAddress(&p_hbuf2, d_hbuf2);
    cudaGetSymbolAddress(&p_h3, d_h3);

    const int NB_E4 = (N_EDGES / 4 + 255) / 256;
    const int NB_N  = (N_NODES + 255) / 256;
    const int NB_T  = (N_NODES + 127) / 128;
    const int NB_M  = (N_NODES + 63) / 64;
    const int NB_W  = (N_NODES * 32 + 255) / 256;

    // fork: gemm_tc (x,W1 only) runs concurrently with the CSR build
    cudaStream_t s2;
    cudaStreamCreateWithFlags(&s2, cudaStreamNonBlocking);
    cudaEvent_t evFork, evJoin;
    cudaEventCreateWithFlags(&evFork, cudaEventDisableTiming);
    cudaEventCreateWithFlags(&evJoin, cudaEventDisableTiming);

    cudaEventRecord(evFork, 0);
    cudaStreamWaitEvent(s2, evFork, 0);
    k_gemm_tc<<<NB_T, 256, 0, s2>>>(x, W1, (__nv_bfloat162*)p_hbuf);
    cudaEventRecord(evJoin, s2);

    // CSR build on the main (capture) stream. d_cnt arrives pre-zeroed
    // (module-load init on the first call; k_agg3 re-zeroes it every call).
    k_count<<<NB_E4, 256>>>(dst4);
    k_node<<<NB_N, 256>>>();
    k_fill<<<NB_E4, 256>>>(src4, dst4);

    // join: aggregation needs both CSR and hbuf
    cudaStreamWaitEvent(0, evJoin, 0);

    k_agg_gemm<<<NB_M, 256>>>((const __nv_bfloat162*)p_hbuf, b1, W2,
                              (__nv_bfloat162*)p_hbuf2);
    k_agg_gemm3<<<NB_W, 256>>>((const __nv_bfloat162*)p_hbuf2, b2, W3, (float*)p_h3);
    k_agg3<<<NB_W, 256>>>((const float*)p_h3, b3, out);

    cudaEventDestroy(evFork);
    cudaEventDestroy(evJoin);
    cudaStreamDestroy(s2);
}